// round 9
// baseline (speedup 1.0000x reference)
#include <cuda_runtime.h>
#include <cstdint>

#define B_   4
#define T_   2048
#define HIN_ 1024
#define H_   16
#define E_   64
#define HE_  (H_ * E_)   // 1024
#define BT_  (B_ * T_)   // 8192

// Persistent scratch (no allocations allowed in kernel_launch).
__device__ float g_Q[BT_ * HE_];
__device__ float g_K[BT_ * HE_];
__device__ float g_V[BT_ * HE_];

// ---------------------------------------------------------------------------
// Packed fp32x2 helpers (Blackwell FFMA2 via PTX f32x2)
// ---------------------------------------------------------------------------
typedef unsigned long long u64;

__device__ __forceinline__ u64 pack2(float lo, float hi) {
    u64 r;
    asm("mov.b64 %0, {%1,%2};" : "=l"(r) : "f"(lo), "f"(hi));
    return r;
}
__device__ __forceinline__ float2 unpack2(u64 v) {
    float2 r;
    asm("mov.b64 {%0,%1}, %2;" : "=f"(r.x), "=f"(r.y) : "l"(v));
    return r;
}
__device__ __forceinline__ void fma2(u64& d, u64 a, u64 b) {
    asm("fma.rn.f32x2 %0, %1, %2, %0;" : "+l"(d) : "l"(a), "l"(b));
}
__device__ __forceinline__ u64 mul2(u64 a, u64 b) {
    u64 r;
    asm("mul.rn.f32x2 %0, %1, %2;" : "=l"(r) : "l"(a), "l"(b));
    return r;
}

// ---------------------------------------------------------------------------
// Projection GEMM: C[M=8192, N=1024] = A[M,K=1024] @ W[K,N], C *= scale.
// 128x128 CTA tile, BK=16, 256 threads, 8x8 micro-tile, double-buffered smem
// (one __syncthreads per k-chunk, LDG prefetch overlapped with compute).
// A-transpose stores use an XOR swizzle (bits 3-4) -> conflict-free.
// Thread covers cols {tx*4..+3} and {64+tx*4..+3} so span reads are 2-wf.
// ---------------------------------------------------------------------------
__global__ __launch_bounds__(256) void proj_gemm(const float* __restrict__ A,
                                                 const float* __restrict__ W,
                                                 int sel, float scale) {
    __shared__ float AsT[2][16][128];   // [buf][k][m-swizzled]
    __shared__ float Ws[2][16][128];    // [buf][k][n]

    float* __restrict__ C = (sel == 0) ? g_Q : (sel == 1) ? g_K : g_V;

    const int tid = threadIdx.x;
    const int ty = tid >> 4;          // 0..15 (8 rows each)
    const int tx = tid & 15;          // 0..15 (4+4 cols each)
    const int bm = blockIdx.y << 7;
    const int bn = blockIdx.x << 7;

    // A loader: 128 rows x 16 k; thread -> row tid/2, 8 k at (tid&1)*8
    const int ar = tid >> 1;
    const int ac = (tid & 1) << 3;
    // W loader: 16 k-rows x 128 cols; thread -> row tid/16, cols (tid&15)*4 and +64
    const int wr = tid >> 4;
    const int wc = (tid & 15) << 2;

    const float* Ap = A + (size_t)(bm + ar) * HIN_ + ac;
    const float* Wp = W + (size_t)wr * HE_ + bn + wc;

    u64 acc[8][4];
#pragma unroll
    for (int i = 0; i < 8; i++)
#pragma unroll
        for (int j = 0; j < 4; j++) acc[i][j] = 0ull;

    // ---- prologue: chunk 0 ----
    float4 av0 = *(const float4*)(Ap);
    float4 av1 = *(const float4*)(Ap + 4);
    float4 wv0 = *(const float4*)(Wp);
    float4 wv1 = *(const float4*)(Wp + 64);
    {
        float av[8] = {av0.x, av0.y, av0.z, av0.w, av1.x, av1.y, av1.z, av1.w};
#pragma unroll
        for (int j = 0; j < 8; j++) {
            int k = ac + j;
            int cx = ((k & 6) << 2) ^ ((k & 8) << 1);
            AsT[0][k][ar ^ cx] = av[j];
        }
        *(float4*)&Ws[0][wr][wc] = wv0;
        *(float4*)&Ws[0][wr][wc + 64] = wv1;
    }
    __syncthreads();

    int buf = 0;
    for (int it = 1; it < 64; it++) {
        // prefetch chunk it
        av0 = *(const float4*)(Ap + it * 16);
        av1 = *(const float4*)(Ap + it * 16 + 4);
        wv0 = *(const float4*)(Wp + (size_t)it * 16 * HE_);
        wv1 = *(const float4*)(Wp + (size_t)it * 16 * HE_ + 64);

        // compute chunk it-1 from buf
#pragma unroll
        for (int kk = 0; kk < 16; kk++) {
            int cx = ((kk & 6) << 2) ^ ((kk & 8) << 1);
            float4 aa0 = *(const float4*)&AsT[buf][kk][(ty << 3) ^ cx];
            float4 aa1 = *(const float4*)&AsT[buf][kk][((ty << 3) + 4) ^ cx];
            float4 ww0 = *(const float4*)&Ws[buf][kk][tx << 2];
            float4 ww1 = *(const float4*)&Ws[buf][kk][64 + (tx << 2)];
            u64 w0 = pack2(ww0.x, ww0.y);
            u64 w1 = pack2(ww0.z, ww0.w);
            u64 w2 = pack2(ww1.x, ww1.y);
            u64 w3 = pack2(ww1.z, ww1.w);
            float a[8] = {aa0.x, aa0.y, aa0.z, aa0.w,
                          aa1.x, aa1.y, aa1.z, aa1.w};
#pragma unroll
            for (int i = 0; i < 8; i++) {
                u64 ad = pack2(a[i], a[i]);
                fma2(acc[i][0], ad, w0);
                fma2(acc[i][1], ad, w1);
                fma2(acc[i][2], ad, w2);
                fma2(acc[i][3], ad, w3);
            }
        }

        // store chunk it into the other buffer
        int nb = buf ^ 1;
        {
            float av[8] = {av0.x, av0.y, av0.z, av0.w,
                           av1.x, av1.y, av1.z, av1.w};
#pragma unroll
            for (int j = 0; j < 8; j++) {
                int k = ac + j;
                int cx = ((k & 6) << 2) ^ ((k & 8) << 1);
                AsT[nb][k][ar ^ cx] = av[j];
            }
            *(float4*)&Ws[nb][wr][wc] = wv0;
            *(float4*)&Ws[nb][wr][wc + 64] = wv1;
        }
        __syncthreads();
        buf = nb;
    }

    // last chunk
#pragma unroll
    for (int kk = 0; kk < 16; kk++) {
        int cx = ((kk & 6) << 2) ^ ((kk & 8) << 1);
        float4 aa0 = *(const float4*)&AsT[buf][kk][(ty << 3) ^ cx];
        float4 aa1 = *(const float4*)&AsT[buf][kk][((ty << 3) + 4) ^ cx];
        float4 ww0 = *(const float4*)&Ws[buf][kk][tx << 2];
        float4 ww1 = *(const float4*)&Ws[buf][kk][64 + (tx << 2)];
        u64 w0 = pack2(ww0.x, ww0.y);
        u64 w1 = pack2(ww0.z, ww0.w);
        u64 w2 = pack2(ww1.x, ww1.y);
        u64 w3 = pack2(ww1.z, ww1.w);
        float a[8] = {aa0.x, aa0.y, aa0.z, aa0.w, aa1.x, aa1.y, aa1.z, aa1.w};
#pragma unroll
        for (int i = 0; i < 8; i++) {
            u64 ad = pack2(a[i], a[i]);
            fma2(acc[i][0], ad, w0);
            fma2(acc[i][1], ad, w1);
            fma2(acc[i][2], ad, w2);
            fma2(acc[i][3], ad, w3);
        }
    }

#pragma unroll
    for (int i = 0; i < 8; i++) {
        float2 p0 = unpack2(acc[i][0]);
        float2 p1 = unpack2(acc[i][1]);
        float2 p2 = unpack2(acc[i][2]);
        float2 p3 = unpack2(acc[i][3]);
        float* Crow = C + (size_t)(bm + (ty << 3) + i) * HE_ + bn;
        *(float4*)(Crow + (tx << 2)) =
            make_float4(p0.x * scale, p0.y * scale, p1.x * scale, p1.y * scale);
        *(float4*)(Crow + 64 + (tx << 2)) =
            make_float4(p2.x * scale, p2.y * scale, p3.x * scale, p3.y * scale);
    }
}

// ---------------------------------------------------------------------------
// Flash attention: one CTA (128 threads) = 64 query rows for a fixed (b, h).
// Q/K transposed tiles XOR-swizzled (as R7). P now goes into a SEPARATE Ps
// buffer: its producers/consumers are the same 16 lanes of one warp, so only
// __syncwarp() is needed -> 2 block syncs per key tile instead of 4.
// Dynamic smem: QsT | KsT | Vs | Ps = 4 x 16 KB = 64 KB.
// ---------------------------------------------------------------------------
__global__ __launch_bounds__(128) void flash_attn(float* __restrict__ Out) {
    extern __shared__ float fsm[];
    float (*QsT)[64] = (float(*)[64])(fsm);            // swizzled [e][qrow]
    float (*KsT)[64] = (float(*)[64])(fsm + 4096);     // swizzled [e][krow]
    float (*Vs)[64]  = (float(*)[64])(fsm + 8192);     // [krow][e]
    float (*Ps)[64]  = (float(*)[64])(fsm + 12288);    // [qrow][krow]

    const int tid = threadIdx.x;
    const int ty = tid >> 4;        // q-row group 0..7 (8 rows each)
    const int tx = tid & 15;        // col group 0..15 (4 cols each)
    const int q0 = blockIdx.x << 6;
    const int h  = blockIdx.y;
    const int b  = blockIdx.z;

    const size_t baseQ  = ((size_t)(b * T_ + q0) * H_ + h) * E_;
    const size_t baseKV = ((size_t)b * T_ * H_ + h) * E_;

    // Load Q tile transposed+swizzled (once per CTA)
    for (int idx = tid; idx < 1024; idx += 128) {
        int row = idx >> 4;
        int t = idx & 15;
        int c = t << 2;
        float4 v = *(const float4*)(g_Q + baseQ + (size_t)row * HE_ + c);
        int col = (((row >> 2) ^ t) << 2) | (row & 3);
        QsT[c + 0][col] = v.x;
        QsT[c + 1][col] = v.y;
        QsT[c + 2][col] = v.z;
        QsT[c + 3][col] = v.w;
    }

    float m[8], l[8];
    u64 o2[8][2];
#pragma unroll
    for (int i = 0; i < 8; i++) {
        m[i] = -1e30f;
        l[i] = 0.f;
        o2[i][0] = 0ull;
        o2[i][1] = 0ull;
    }

    for (int k0 = 0; k0 < T_; k0 += 64) {
        __syncthreads();   // prev tile fully consumed (and Q visible, 1st iter)
        for (int idx = tid; idx < 1024; idx += 128) {
            int row = idx >> 4;
            int t = idx & 15;
            int c = t << 2;
            size_t g = baseKV + (size_t)(k0 + row) * HE_ + c;
            float4 kv = *(const float4*)(g_K + g);
            int col = (((row >> 2) ^ t) << 2) | (row & 3);
            KsT[c + 0][col] = kv.x;
            KsT[c + 1][col] = kv.y;
            KsT[c + 2][col] = kv.z;
            KsT[c + 3][col] = kv.w;
            *(float4*)&Vs[row][c] = *(const float4*)(g_V + g);
        }
        __syncthreads();

        // S = Q K^T: 8x4 outer products over e (swizzled reads)
        u64 s2[8][2];
#pragma unroll
        for (int i = 0; i < 8; i++) { s2[i][0] = 0ull; s2[i][1] = 0ull; }
#pragma unroll 4
        for (int x = 0; x < 16; x++) {
#pragma unroll
            for (int ee = 0; ee < 4; ee++) {
                int e = (x << 2) + ee;
                float4 qa = *(const float4*)&QsT[e][((2 * ty) ^ x) << 2];
                float4 qb = *(const float4*)&QsT[e][((2 * ty + 1) ^ x) << 2];
                float4 k4 = *(const float4*)&KsT[e][(tx ^ x) << 2];
                u64 kp0 = pack2(k4.x, k4.y);
                u64 kp1 = pack2(k4.z, k4.w);
                float q[8] = {qa.x, qa.y, qa.z, qa.w, qb.x, qb.y, qb.z, qb.w};
#pragma unroll
                for (int i = 0; i < 8; i++) {
                    u64 qd = pack2(q[i], q[i]);
                    fma2(s2[i][0], qd, kp0);
                    fma2(s2[i][1], qd, kp1);
                }
            }
        }

        // Online softmax: reduce across the 16 tx lanes per q row
        float s[8][4];
#pragma unroll
        for (int i = 0; i < 8; i++) {
            float2 p0 = unpack2(s2[i][0]);
            float2 p1 = unpack2(s2[i][1]);
            s[i][0] = p0.x; s[i][1] = p0.y; s[i][2] = p1.x; s[i][3] = p1.y;
        }
#pragma unroll
        for (int i = 0; i < 8; i++) {
            float mx = fmaxf(fmaxf(s[i][0], s[i][1]), fmaxf(s[i][2], s[i][3]));
#pragma unroll
            for (int off = 8; off >= 1; off >>= 1)
                mx = fmaxf(mx, __shfl_xor_sync(0xffffffffu, mx, off));
            float mnew = fmaxf(m[i], mx);
            float corr = __expf(m[i] - mnew);
            float rs = 0.f;
#pragma unroll
            for (int j = 0; j < 4; j++) {
                s[i][j] = __expf(s[i][j] - mnew);
                rs += s[i][j];
            }
#pragma unroll
            for (int off = 8; off >= 1; off >>= 1)
                rs += __shfl_xor_sync(0xffffffffu, rs, off);
            l[i] = l[i] * corr + rs;
            m[i] = mnew;
            u64 cd = pack2(corr, corr);
            o2[i][0] = mul2(o2[i][0], cd);
            o2[i][1] = mul2(o2[i][1], cd);
        }

        // Write P to its own buffer — warp-scope exchange only
#pragma unroll
        for (int i = 0; i < 8; i++)
            *(float4*)&Ps[(ty << 3) + i][tx << 2] =
                make_float4(s[i][0], s[i][1], s[i][2], s[i][3]);
        __syncwarp();

        // O += P @ V  (k unrolled by 4; p reads are float4 broadcasts)
#pragma unroll 4
        for (int k = 0; k < 64; k += 4) {
            u64 vp[4][2];
#pragma unroll
            for (int kk = 0; kk < 4; kk++) {
                float4 v4 = *(const float4*)&Vs[k + kk][tx << 2];  // span
                vp[kk][0] = pack2(v4.x, v4.y);
                vp[kk][1] = pack2(v4.z, v4.w);
            }
#pragma unroll
            for (int i = 0; i < 8; i++) {
                float4 p4 = *(const float4*)&Ps[(ty << 3) + i][k];  // broadcast
                float p[4] = {p4.x, p4.y, p4.z, p4.w};
#pragma unroll
                for (int kk = 0; kk < 4; kk++) {
                    u64 pd = pack2(p[kk], p[kk]);
                    fma2(o2[i][0], pd, vp[kk][0]);
                    fma2(o2[i][1], pd, vp[kk][1]);
                }
            }
        }
    }

#pragma unroll
    for (int i = 0; i < 8; i++) {
        float inv = 1.0f / l[i];
        float2 p0 = unpack2(o2[i][0]);
        float2 p1 = unpack2(o2[i][1]);
        float4 r = make_float4(p0.x * inv, p0.y * inv, p1.x * inv, p1.y * inv);
        *(float4*)&Out[((size_t)(b * T_ + q0 + (ty << 3) + i) * H_ + h) * E_ +
                       (tx << 2)] = r;
    }
}

// ---------------------------------------------------------------------------
extern "C" void kernel_launch(void* const* d_in, const int* in_sizes, int n_in,
                              void* d_out, int out_size) {
    const float* query     = (const float*)d_in[0];
    const float* key_value = (const float*)d_in[1];
    const float* Wq        = (const float*)d_in[2];
    const float* Wk        = (const float*)d_in[3];
    const float* Wv        = (const float*)d_in[4];
    float* out = (float*)d_out;

    const float scale = 0.35355339059327379f;  // 64^(-1/4)

    dim3 gproj(HE_ / 128, BT_ / 128);          // (8, 64)
    proj_gemm<<<gproj, 256>>>(query,     Wq, 0, scale);
    proj_gemm<<<gproj, 256>>>(key_value, Wk, 1, scale);
    proj_gemm<<<gproj, 256>>>(key_value, Wv, 2, 1.0f);

    static int smem_set = 0;
    if (!smem_set) {
        cudaFuncSetAttribute(flash_attn,
                             cudaFuncAttributeMaxDynamicSharedMemorySize,
                             65536);
        smem_set = 1;
    }
    dim3 gattn(T_ / 64, H_, B_);               // (32, 16, 4)
    flash_attn<<<gattn, 128, 65536>>>(out);
}

// round 10
// speedup vs baseline: 1.6118x; 1.6118x over previous
#include <cuda_runtime.h>
#include <cstdint>

#define B_   4
#define T_   2048
#define HIN_ 1024
#define H_   16
#define E_   64
#define HE_  (H_ * E_)   // 1024
#define BT_  (B_ * T_)   // 8192

// Persistent scratch (no allocations allowed in kernel_launch).
__device__ float g_Q[BT_ * HE_];
__device__ float g_K[BT_ * HE_];
__device__ float g_V[BT_ * HE_];

// ---------------------------------------------------------------------------
// Packed fp32x2 helpers (Blackwell FFMA2 via PTX f32x2)
// ---------------------------------------------------------------------------
typedef unsigned long long u64;

__device__ __forceinline__ u64 pack2(float lo, float hi) {
    u64 r;
    asm("mov.b64 %0, {%1,%2};" : "=l"(r) : "f"(lo), "f"(hi));
    return r;
}
__device__ __forceinline__ float2 unpack2(u64 v) {
    float2 r;
    asm("mov.b64 {%0,%1}, %2;" : "=f"(r.x), "=f"(r.y) : "l"(v));
    return r;
}
__device__ __forceinline__ void fma2(u64& d, u64 a, u64 b) {
    asm("fma.rn.f32x2 %0, %1, %2, %0;" : "+l"(d) : "l"(a), "l"(b));
}
__device__ __forceinline__ u64 mul2(u64 a, u64 b) {
    u64 r;
    asm("mul.rn.f32x2 %0, %1, %2;" : "=l"(r) : "l"(a), "l"(b));
    return r;
}

// ---------------------------------------------------------------------------
// Projection GEMM (all three in one launch, sel = blockIdx.z):
//   C[8192,1024] = A @ W, C *= scale.
// 64x64 CTA tile, BK=16, 128 threads, 8x4 micro-tile, DOUBLE-BUFFERED smem:
// one __syncthreads per k-chunk, LDG prefetch overlapped with compute.
// AsT stores swizzled (conflict-free); Ws rows padded to 68 floats so the
// store banks are spread by wr. Total smem = 2*(16*64 + 16*68)*4 = 16.9 KB.
// ---------------------------------------------------------------------------
__global__ __launch_bounds__(128) void proj_gemm(const float* __restrict__ Aq,
                                                 const float* __restrict__ Akv,
                                                 const float* __restrict__ Wq,
                                                 const float* __restrict__ Wk,
                                                 const float* __restrict__ Wv,
                                                 float scale) {
    __shared__ float AsT[2][16][64];   // [buf][k][m-swizzled]
    __shared__ float Ws[2][16][68];    // [buf][k][n], padded rows

    const int sel = blockIdx.z;
    const float* __restrict__ A = (sel == 0) ? Aq : Akv;
    const float* __restrict__ W = (sel == 0) ? Wq : (sel == 1) ? Wk : Wv;
    float* __restrict__ C = (sel == 0) ? g_Q : (sel == 1) ? g_K : g_V;
    const float cs = (sel == 2) ? 1.0f : scale;

    const int tid = threadIdx.x;
    const int ty = tid >> 4;          // 0..7  (8 rows each)
    const int tx = tid & 15;          // 0..15 (4 cols each)
    const int bm = blockIdx.y << 6;
    const int bn = blockIdx.x << 6;

    // A loader: 64 rows x 16 k; thread -> row tid/2, 8 k at (tid&1)*8
    const int ar = tid >> 1;
    const int ac = (tid & 1) << 3;
    // W loader: 16 k-rows x 64 cols; thread -> row tid/8, 8 cols at (tid&7)*8
    const int wr = tid >> 3;
    const int wc = (tid & 7) << 3;

    const float* Ap = A + (size_t)(bm + ar) * HIN_ + ac;
    const float* Wp = W + (size_t)wr * HE_ + bn + wc;

    u64 acc[8][2];
#pragma unroll
    for (int i = 0; i < 8; i++) { acc[i][0] = 0ull; acc[i][1] = 0ull; }

    // swizzle: storage col of (k, m) = m ^ (((k>>2)&3)<<2)
    // ---- prologue: chunk 0 ----
    {
        float4 a0 = *(const float4*)(Ap);
        float4 a1 = *(const float4*)(Ap + 4);
        float4 w0 = *(const float4*)(Wp);
        float4 w1 = *(const float4*)(Wp + 4);
        float av[8] = {a0.x, a0.y, a0.z, a0.w, a1.x, a1.y, a1.z, a1.w};
#pragma unroll
        for (int j = 0; j < 8; j++) {
            int k = ac + j;
            AsT[0][k][ar ^ (((k >> 2) & 3) << 2)] = av[j];
        }
        *(float4*)&Ws[0][wr][wc] = w0;
        *(float4*)&Ws[0][wr][wc + 4] = w1;
    }
    __syncthreads();

    int buf = 0;
    for (int it = 1; it <= 64; it++) {
        float4 a0, a1, w0, w1;
        if (it < 64) {   // prefetch chunk it
            a0 = *(const float4*)(Ap + it * 16);
            a1 = *(const float4*)(Ap + it * 16 + 4);
            w0 = *(const float4*)(Wp + (size_t)it * 16 * HE_);
            w1 = *(const float4*)(Wp + (size_t)it * 16 * HE_ + 4);
        }

        // compute chunk it-1 from buf
#pragma unroll
        for (int kk = 0; kk < 16; kk++) {
            int cx = ((kk >> 2) & 3) << 2;
            float4 aa0 = *(const float4*)&AsT[buf][kk][(ty << 3) ^ cx];
            float4 aa1 = *(const float4*)&AsT[buf][kk][((ty << 3) + 4) ^ cx];
            float4 w4 = *(const float4*)&Ws[buf][kk][tx << 2];
            u64 wp0 = pack2(w4.x, w4.y);
            u64 wp1 = pack2(w4.z, w4.w);
            float a[8] = {aa0.x, aa0.y, aa0.z, aa0.w,
                          aa1.x, aa1.y, aa1.z, aa1.w};
#pragma unroll
            for (int i = 0; i < 8; i++) {
                u64 ad = pack2(a[i], a[i]);
                fma2(acc[i][0], ad, wp0);
                fma2(acc[i][1], ad, wp1);
            }
        }

        if (it < 64) {
            int nb = buf ^ 1;
            float av[8] = {a0.x, a0.y, a0.z, a0.w, a1.x, a1.y, a1.z, a1.w};
#pragma unroll
            for (int j = 0; j < 8; j++) {
                int k = ac + j;
                AsT[nb][k][ar ^ (((k >> 2) & 3) << 2)] = av[j];
            }
            *(float4*)&Ws[nb][wr][wc] = w0;
            *(float4*)&Ws[nb][wr][wc + 4] = w1;
            __syncthreads();
            buf = nb;
        }
    }

#pragma unroll
    for (int i = 0; i < 8; i++) {
        float2 p0 = unpack2(acc[i][0]);
        float2 p1 = unpack2(acc[i][1]);
        float4 r = make_float4(p0.x * cs, p0.y * cs, p1.x * cs, p1.y * cs);
        *(float4*)&C[(size_t)(bm + (ty << 3) + i) * HE_ + bn + (tx << 2)] = r;
    }
}

// ---------------------------------------------------------------------------
// Flash attention (exact R7 kernel — known good at 1.51 ms):
// one CTA (128 threads) = 64 query rows for a fixed (b, h).
// Q/K transposed tiles XOR-swizzled; KsT reused (plain layout) for P.
// ---------------------------------------------------------------------------
__global__ __launch_bounds__(128) void flash_attn(float* __restrict__ Out) {
    __shared__ float QsT[64][64];   // swizzled [e][qrow]
    __shared__ float KsT[64][64];   // swizzled [e][krow]; reused plain as P
    __shared__ float Vs[64][64];    // [krow][e]

    const int tid = threadIdx.x;
    const int ty = tid >> 4;        // q-row group 0..7 (8 rows each)
    const int tx = tid & 15;        // col group 0..15 (4 cols each)
    const int q0 = blockIdx.x << 6;
    const int h  = blockIdx.y;
    const int b  = blockIdx.z;

    const size_t baseQ  = ((size_t)(b * T_ + q0) * H_ + h) * E_;
    const size_t baseKV = ((size_t)b * T_ * H_ + h) * E_;

    for (int idx = tid; idx < 1024; idx += 128) {
        int row = idx >> 4;
        int t = idx & 15;
        int c = t << 2;
        float4 v = *(const float4*)(g_Q + baseQ + (size_t)row * HE_ + c);
        int col = (((row >> 2) ^ t) << 2) | (row & 3);
        QsT[c + 0][col] = v.x;
        QsT[c + 1][col] = v.y;
        QsT[c + 2][col] = v.z;
        QsT[c + 3][col] = v.w;
    }

    float m[8], l[8];
    u64 o2[8][2];
#pragma unroll
    for (int i = 0; i < 8; i++) {
        m[i] = -1e30f;
        l[i] = 0.f;
        o2[i][0] = 0ull;
        o2[i][1] = 0ull;
    }

    for (int k0 = 0; k0 < T_; k0 += 64) {
        __syncthreads();
        for (int idx = tid; idx < 1024; idx += 128) {
            int row = idx >> 4;
            int t = idx & 15;
            int c = t << 2;
            size_t g = baseKV + (size_t)(k0 + row) * HE_ + c;
            float4 kv = *(const float4*)(g_K + g);
            int col = (((row >> 2) ^ t) << 2) | (row & 3);
            KsT[c + 0][col] = kv.x;
            KsT[c + 1][col] = kv.y;
            KsT[c + 2][col] = kv.z;
            KsT[c + 3][col] = kv.w;
            *(float4*)&Vs[row][c] = *(const float4*)(g_V + g);
        }
        __syncthreads();

        // S = Q K^T: 8x4 outer products over e (swizzled reads)
        u64 s2[8][2];
#pragma unroll
        for (int i = 0; i < 8; i++) { s2[i][0] = 0ull; s2[i][1] = 0ull; }
#pragma unroll 4
        for (int x = 0; x < 16; x++) {
#pragma unroll
            for (int ee = 0; ee < 4; ee++) {
                int e = (x << 2) + ee;
                float4 qa = *(const float4*)&QsT[e][((2 * ty) ^ x) << 2];
                float4 qb = *(const float4*)&QsT[e][((2 * ty + 1) ^ x) << 2];
                float4 k4 = *(const float4*)&KsT[e][(tx ^ x) << 2];
                u64 kp0 = pack2(k4.x, k4.y);
                u64 kp1 = pack2(k4.z, k4.w);
                float q[8] = {qa.x, qa.y, qa.z, qa.w, qb.x, qb.y, qb.z, qb.w};
#pragma unroll
                for (int i = 0; i < 8; i++) {
                    u64 qd = pack2(q[i], q[i]);
                    fma2(s2[i][0], qd, kp0);
                    fma2(s2[i][1], qd, kp1);
                }
            }
        }

        // Online softmax: reduce across the 16 tx lanes per q row
        float s[8][4];
#pragma unroll
        for (int i = 0; i < 8; i++) {
            float2 p0 = unpack2(s2[i][0]);
            float2 p1 = unpack2(s2[i][1]);
            s[i][0] = p0.x; s[i][1] = p0.y; s[i][2] = p1.x; s[i][3] = p1.y;
        }
#pragma unroll
        for (int i = 0; i < 8; i++) {
            float mx = fmaxf(fmaxf(s[i][0], s[i][1]), fmaxf(s[i][2], s[i][3]));
#pragma unroll
            for (int off = 8; off >= 1; off >>= 1)
                mx = fmaxf(mx, __shfl_xor_sync(0xffffffffu, mx, off));
            float mnew = fmaxf(m[i], mx);
            float corr = __expf(m[i] - mnew);
            float rs = 0.f;
#pragma unroll
            for (int j = 0; j < 4; j++) {
                s[i][j] = __expf(s[i][j] - mnew);
                rs += s[i][j];
            }
#pragma unroll
            for (int off = 8; off >= 1; off >>= 1)
                rs += __shfl_xor_sync(0xffffffffu, rs, off);
            l[i] = l[i] * corr + rs;
            m[i] = mnew;
            u64 cd = pack2(corr, corr);
            o2[i][0] = mul2(o2[i][0], cd);
            o2[i][1] = mul2(o2[i][1], cd);
        }

        __syncthreads();   // done reading KsT as K
#pragma unroll
        for (int i = 0; i < 8; i++)
            *(float4*)&KsT[(ty << 3) + i][tx << 2] =
                make_float4(s[i][0], s[i][1], s[i][2], s[i][3]);
        __syncthreads();   // P visible (plain layout)

        // O += P @ V  (k unrolled by 4; p reads are float4 broadcasts)
#pragma unroll 4
        for (int k = 0; k < 64; k += 4) {
            u64 vp[4][2];
#pragma unroll
            for (int kk = 0; kk < 4; kk++) {
                float4 v4 = *(const float4*)&Vs[k + kk][tx << 2];  // span
                vp[kk][0] = pack2(v4.x, v4.y);
                vp[kk][1] = pack2(v4.z, v4.w);
            }
#pragma unroll
            for (int i = 0; i < 8; i++) {
                float4 p4 = *(const float4*)&KsT[(ty << 3) + i][k]; // broadcast
                float p[4] = {p4.x, p4.y, p4.z, p4.w};
#pragma unroll
                for (int kk = 0; kk < 4; kk++) {
                    u64 pd = pack2(p[kk], p[kk]);
                    fma2(o2[i][0], pd, vp[kk][0]);
                    fma2(o2[i][1], pd, vp[kk][1]);
                }
            }
        }
    }

#pragma unroll
    for (int i = 0; i < 8; i++) {
        float inv = 1.0f / l[i];
        float2 p0 = unpack2(o2[i][0]);
        float2 p1 = unpack2(o2[i][1]);
        float4 r = make_float4(p0.x * inv, p0.y * inv, p1.x * inv, p1.y * inv);
        *(float4*)&Out[((size_t)(b * T_ + q0 + (ty << 3) + i) * H_ + h) * E_ +
                       (tx << 2)] = r;
    }
}

// ---------------------------------------------------------------------------
extern "C" void kernel_launch(void* const* d_in, const int* in_sizes, int n_in,
                              void* d_out, int out_size) {
    const float* query     = (const float*)d_in[0];
    const float* key_value = (const float*)d_in[1];
    const float* Wq        = (const float*)d_in[2];
    const float* Wk        = (const float*)d_in[3];
    const float* Wv        = (const float*)d_in[4];
    float* out = (float*)d_out;

    const float scale = 0.35355339059327379f;  // 64^(-1/4)

    dim3 gproj(HE_ / 64, BT_ / 64, 3);         // (16, 128, 3)
    proj_gemm<<<gproj, 128>>>(query, key_value, Wq, Wk, Wv, scale);

    dim3 gattn(T_ / 64, H_, B_);               // (32, 16, 4)
    flash_attn<<<gattn, 128>>>(out);
}

// round 11
// speedup vs baseline: 1.6343x; 1.0140x over previous
#include <cuda_runtime.h>
#include <cstdint>

#define B_   4
#define T_   2048
#define HIN_ 1024
#define H_   16
#define E_   64
#define HE_  (H_ * E_)   // 1024
#define BT_  (B_ * T_)   // 8192
#define NSPLIT 2
#define TSPLIT (T_ / NSPLIT)   // 1024 keys per split

// Persistent scratch (no allocations allowed in kernel_launch).
__device__ float g_Q[BT_ * HE_];
__device__ float g_K[BT_ * HE_];
__device__ float g_V[BT_ * HE_];
__device__ float g_Op[NSPLIT * BT_ * HE_];   // unnormalized partial O
__device__ float g_m[NSPLIT * BT_ * H_];     // running max per row
__device__ float g_l[NSPLIT * BT_ * H_];     // running sum per row

// ---------------------------------------------------------------------------
// Packed fp32x2 helpers (Blackwell FFMA2 via PTX f32x2)
// ---------------------------------------------------------------------------
typedef unsigned long long u64;

__device__ __forceinline__ u64 pack2(float lo, float hi) {
    u64 r;
    asm("mov.b64 %0, {%1,%2};" : "=l"(r) : "f"(lo), "f"(hi));
    return r;
}
__device__ __forceinline__ float2 unpack2(u64 v) {
    float2 r;
    asm("mov.b64 {%0,%1}, %2;" : "=f"(r.x), "=f"(r.y) : "l"(v));
    return r;
}
__device__ __forceinline__ void fma2(u64& d, u64 a, u64 b) {
    asm("fma.rn.f32x2 %0, %1, %2, %0;" : "+l"(d) : "l"(a), "l"(b));
}
__device__ __forceinline__ u64 mul2(u64 a, u64 b) {
    u64 r;
    asm("mul.rn.f32x2 %0, %1, %2;" : "=l"(r) : "l"(a), "l"(b));
    return r;
}

// ---------------------------------------------------------------------------
// Projection GEMM (all three in one launch, sel = blockIdx.z) — R10 kernel.
// ---------------------------------------------------------------------------
__global__ __launch_bounds__(128) void proj_gemm(const float* __restrict__ Aq,
                                                 const float* __restrict__ Akv,
                                                 const float* __restrict__ Wq,
                                                 const float* __restrict__ Wk,
                                                 const float* __restrict__ Wv,
                                                 float scale) {
    __shared__ float AsT[2][16][64];   // [buf][k][m-swizzled]
    __shared__ float Ws[2][16][68];    // [buf][k][n], padded rows

    const int sel = blockIdx.z;
    const float* __restrict__ A = (sel == 0) ? Aq : Akv;
    const float* __restrict__ W = (sel == 0) ? Wq : (sel == 1) ? Wk : Wv;
    float* __restrict__ C = (sel == 0) ? g_Q : (sel == 1) ? g_K : g_V;
    const float cs = (sel == 2) ? 1.0f : scale;

    const int tid = threadIdx.x;
    const int ty = tid >> 4;
    const int tx = tid & 15;
    const int bm = blockIdx.y << 6;
    const int bn = blockIdx.x << 6;

    const int ar = tid >> 1;
    const int ac = (tid & 1) << 3;
    const int wr = tid >> 3;
    const int wc = (tid & 7) << 3;

    const float* Ap = A + (size_t)(bm + ar) * HIN_ + ac;
    const float* Wp = W + (size_t)wr * HE_ + bn + wc;

    u64 acc[8][2];
#pragma unroll
    for (int i = 0; i < 8; i++) { acc[i][0] = 0ull; acc[i][1] = 0ull; }

    {
        float4 a0 = *(const float4*)(Ap);
        float4 a1 = *(const float4*)(Ap + 4);
        float4 w0 = *(const float4*)(Wp);
        float4 w1 = *(const float4*)(Wp + 4);
        float av[8] = {a0.x, a0.y, a0.z, a0.w, a1.x, a1.y, a1.z, a1.w};
#pragma unroll
        for (int j = 0; j < 8; j++) {
            int k = ac + j;
            AsT[0][k][ar ^ (((k >> 2) & 3) << 2)] = av[j];
        }
        *(float4*)&Ws[0][wr][wc] = w0;
        *(float4*)&Ws[0][wr][wc + 4] = w1;
    }
    __syncthreads();

    int buf = 0;
    for (int it = 1; it <= 64; it++) {
        float4 a0, a1, w0, w1;
        if (it < 64) {
            a0 = *(const float4*)(Ap + it * 16);
            a1 = *(const float4*)(Ap + it * 16 + 4);
            w0 = *(const float4*)(Wp + (size_t)it * 16 * HE_);
            w1 = *(const float4*)(Wp + (size_t)it * 16 * HE_ + 4);
        }

#pragma unroll
        for (int kk = 0; kk < 16; kk++) {
            int cx = ((kk >> 2) & 3) << 2;
            float4 aa0 = *(const float4*)&AsT[buf][kk][(ty << 3) ^ cx];
            float4 aa1 = *(const float4*)&AsT[buf][kk][((ty << 3) + 4) ^ cx];
            float4 w4 = *(const float4*)&Ws[buf][kk][tx << 2];
            u64 wp0 = pack2(w4.x, w4.y);
            u64 wp1 = pack2(w4.z, w4.w);
            float a[8] = {aa0.x, aa0.y, aa0.z, aa0.w,
                          aa1.x, aa1.y, aa1.z, aa1.w};
#pragma unroll
            for (int i = 0; i < 8; i++) {
                u64 ad = pack2(a[i], a[i]);
                fma2(acc[i][0], ad, wp0);
                fma2(acc[i][1], ad, wp1);
            }
        }

        if (it < 64) {
            int nb = buf ^ 1;
            float av[8] = {a0.x, a0.y, a0.z, a0.w, a1.x, a1.y, a1.z, a1.w};
#pragma unroll
            for (int j = 0; j < 8; j++) {
                int k = ac + j;
                AsT[nb][k][ar ^ (((k >> 2) & 3) << 2)] = av[j];
            }
            *(float4*)&Ws[nb][wr][wc] = w0;
            *(float4*)&Ws[nb][wr][wc + 4] = w1;
            __syncthreads();
            buf = nb;
        }
    }

#pragma unroll
    for (int i = 0; i < 8; i++) {
        float2 p0 = unpack2(acc[i][0]);
        float2 p1 = unpack2(acc[i][1]);
        float4 r = make_float4(p0.x * cs, p0.y * cs, p1.x * cs, p1.y * cs);
        *(float4*)&C[(size_t)(bm + (ty << 3) + i) * HE_ + bn + (tx << 2)] = r;
    }
}

// ---------------------------------------------------------------------------
// Flash attention, split-K: one CTA = 64 q-rows x 1024 keys for (b, h, split).
// Writes UNNORMALIZED partial O and per-row (m, l); combine kernel merges.
// Core compute identical to the R10 kernel.
// ---------------------------------------------------------------------------
__global__ __launch_bounds__(128) void flash_attn_split() {
    __shared__ float QsT[64][64];   // swizzled [e][qrow]
    __shared__ float KsT[64][64];   // swizzled [e][krow]; reused plain as P
    __shared__ float Vs[64][64];    // [krow][e]

    const int tid = threadIdx.x;
    const int ty = tid >> 4;        // q-row group 0..7 (8 rows each)
    const int tx = tid & 15;        // col group 0..15 (4 cols each)
    const int q0 = blockIdx.x << 6;
    const int h  = blockIdx.y;
    const int b  = blockIdx.z >> 1;
    const int sp = blockIdx.z & 1;

    const size_t baseQ  = ((size_t)(b * T_ + q0) * H_ + h) * E_;
    const size_t baseKV = ((size_t)(b * T_ + sp * TSPLIT) * H_ + h) * E_;

    for (int idx = tid; idx < 1024; idx += 128) {
        int row = idx >> 4;
        int t = idx & 15;
        int c = t << 2;
        float4 v = *(const float4*)(g_Q + baseQ + (size_t)row * HE_ + c);
        int col = (((row >> 2) ^ t) << 2) | (row & 3);
        QsT[c + 0][col] = v.x;
        QsT[c + 1][col] = v.y;
        QsT[c + 2][col] = v.z;
        QsT[c + 3][col] = v.w;
    }

    float m[8], l[8];
    u64 o2[8][2];
#pragma unroll
    for (int i = 0; i < 8; i++) {
        m[i] = -1e30f;
        l[i] = 0.f;
        o2[i][0] = 0ull;
        o2[i][1] = 0ull;
    }

    for (int k0 = 0; k0 < TSPLIT; k0 += 64) {
        __syncthreads();
        for (int idx = tid; idx < 1024; idx += 128) {
            int row = idx >> 4;
            int t = idx & 15;
            int c = t << 2;
            size_t g = baseKV + (size_t)(k0 + row) * HE_ + c;
            float4 kv = *(const float4*)(g_K + g);
            int col = (((row >> 2) ^ t) << 2) | (row & 3);
            KsT[c + 0][col] = kv.x;
            KsT[c + 1][col] = kv.y;
            KsT[c + 2][col] = kv.z;
            KsT[c + 3][col] = kv.w;
            *(float4*)&Vs[row][c] = *(const float4*)(g_V + g);
        }
        __syncthreads();

        // S = Q K^T: 8x4 outer products over e (swizzled reads)
        u64 s2[8][2];
#pragma unroll
        for (int i = 0; i < 8; i++) { s2[i][0] = 0ull; s2[i][1] = 0ull; }
#pragma unroll 4
        for (int x = 0; x < 16; x++) {
#pragma unroll
            for (int ee = 0; ee < 4; ee++) {
                int e = (x << 2) + ee;
                float4 qa = *(const float4*)&QsT[e][((2 * ty) ^ x) << 2];
                float4 qb = *(const float4*)&QsT[e][((2 * ty + 1) ^ x) << 2];
                float4 k4 = *(const float4*)&KsT[e][(tx ^ x) << 2];
                u64 kp0 = pack2(k4.x, k4.y);
                u64 kp1 = pack2(k4.z, k4.w);
                float q[8] = {qa.x, qa.y, qa.z, qa.w, qb.x, qb.y, qb.z, qb.w};
#pragma unroll
                for (int i = 0; i < 8; i++) {
                    u64 qd = pack2(q[i], q[i]);
                    fma2(s2[i][0], qd, kp0);
                    fma2(s2[i][1], qd, kp1);
                }
            }
        }

        // Online softmax: reduce across the 16 tx lanes per q row
        float s[8][4];
#pragma unroll
        for (int i = 0; i < 8; i++) {
            float2 p0 = unpack2(s2[i][0]);
            float2 p1 = unpack2(s2[i][1]);
            s[i][0] = p0.x; s[i][1] = p0.y; s[i][2] = p1.x; s[i][3] = p1.y;
        }
#pragma unroll
        for (int i = 0; i < 8; i++) {
            float mx = fmaxf(fmaxf(s[i][0], s[i][1]), fmaxf(s[i][2], s[i][3]));
#pragma unroll
            for (int off = 8; off >= 1; off >>= 1)
                mx = fmaxf(mx, __shfl_xor_sync(0xffffffffu, mx, off));
            float mnew = fmaxf(m[i], mx);
            float corr = __expf(m[i] - mnew);
            float rs = 0.f;
#pragma unroll
            for (int j = 0; j < 4; j++) {
                s[i][j] = __expf(s[i][j] - mnew);
                rs += s[i][j];
            }
#pragma unroll
            for (int off = 8; off >= 1; off >>= 1)
                rs += __shfl_xor_sync(0xffffffffu, rs, off);
            l[i] = l[i] * corr + rs;
            m[i] = mnew;
            u64 cd = pack2(corr, corr);
            o2[i][0] = mul2(o2[i][0], cd);
            o2[i][1] = mul2(o2[i][1], cd);
        }

        __syncthreads();   // done reading KsT as K
#pragma unroll
        for (int i = 0; i < 8; i++)
            *(float4*)&KsT[(ty << 3) + i][tx << 2] =
                make_float4(s[i][0], s[i][1], s[i][2], s[i][3]);
        __syncthreads();   // P visible (plain layout)

        // O += P @ V
#pragma unroll 4
        for (int k = 0; k < 64; k += 4) {
            u64 vp[4][2];
#pragma unroll
            for (int kk = 0; kk < 4; kk++) {
                float4 v4 = *(const float4*)&Vs[k + kk][tx << 2];
                vp[kk][0] = pack2(v4.x, v4.y);
                vp[kk][1] = pack2(v4.z, v4.w);
            }
#pragma unroll
            for (int i = 0; i < 8; i++) {
                float4 p4 = *(const float4*)&KsT[(ty << 3) + i][k];
                float p[4] = {p4.x, p4.y, p4.z, p4.w};
#pragma unroll
                for (int kk = 0; kk < 4; kk++) {
                    u64 pd = pack2(p[kk], p[kk]);
                    fma2(o2[i][0], pd, vp[kk][0]);
                    fma2(o2[i][1], pd, vp[kk][1]);
                }
            }
        }
    }

    // Write unnormalized partials + (m, l)
    const size_t opBase = (size_t)sp * BT_ * HE_;
    const size_t mlBase = (size_t)sp * BT_ * H_;
#pragma unroll
    for (int i = 0; i < 8; i++) {
        int row = q0 + (ty << 3) + i;
        float2 p0 = unpack2(o2[i][0]);
        float2 p1 = unpack2(o2[i][1]);
        *(float4*)&g_Op[opBase + ((size_t)(b * T_ + row) * H_ + h) * E_ +
                        (tx << 2)] = make_float4(p0.x, p0.y, p1.x, p1.y);
        if (tx == 0) {
            size_t mi = mlBase + (size_t)(b * T_ + row) * H_ + h;
            g_m[mi] = m[i];
            g_l[mi] = l[i];
        }
    }
}

// ---------------------------------------------------------------------------
// Combine: Out = (sum_s e^{m_s-M} O_s) / (sum_s e^{m_s-M} l_s)
// One float4 of output per thread. Layouts of g_Op and Out are identical.
// ---------------------------------------------------------------------------
__global__ __launch_bounds__(256) void flash_combine(float* __restrict__ Out) {
    int idx = blockIdx.x * 256 + threadIdx.x;   // float4 index
    int rowh = idx >> 4;                         // (b*T+t)*H + h
    float m0 = g_m[rowh];
    float m1 = g_m[BT_ * H_ + rowh];
    float l0 = g_l[rowh];
    float l1 = g_l[BT_ * H_ + rowh];
    float M = fmaxf(m0, m1);
    float w0 = __expf(m0 - M);
    float w1 = __expf(m1 - M);
    float inv = 1.0f / (l0 * w0 + l1 * w1);

    const float4* Op4 = (const float4*)g_Op;
    float4 o0 = Op4[idx];
    float4 o1 = Op4[(BT_ * HE_ / 4) + idx];
    float4 r;
    r.x = (o0.x * w0 + o1.x * w1) * inv;
    r.y = (o0.y * w0 + o1.y * w1) * inv;
    r.z = (o0.z * w0 + o1.z * w1) * inv;
    r.w = (o0.w * w0 + o1.w * w1) * inv;
    ((float4*)Out)[idx] = r;
}

// ---------------------------------------------------------------------------
extern "C" void kernel_launch(void* const* d_in, const int* in_sizes, int n_in,
                              void* d_out, int out_size) {
    const float* query     = (const float*)d_in[0];
    const float* key_value = (const float*)d_in[1];
    const float* Wq        = (const float*)d_in[2];
    const float* Wk        = (const float*)d_in[3];
    const float* Wv        = (const float*)d_in[4];
    float* out = (float*)d_out;

    const float scale = 0.35355339059327379f;  // 64^(-1/4)

    dim3 gproj(HE_ / 64, BT_ / 64, 3);         // (16, 128, 3)
    proj_gemm<<<gproj, 128>>>(query, key_value, Wq, Wk, Wv, scale);

    dim3 gattn(T_ / 64, H_, B_ * NSPLIT);      // (32, 16, 8)
    flash_attn_split<<<gattn, 128>>>();

    flash_combine<<<BT_ * HE_ / 4 / 256, 256>>>(out);
}

// round 12
// speedup vs baseline: 1.6371x; 1.0017x over previous
#include <cuda_runtime.h>
#include <cstdint>

#define B_   4
#define T_   2048
#define HIN_ 1024
#define H_   16
#define E_   64
#define HE_  (H_ * E_)   // 1024
#define BT_  (B_ * T_)   // 8192
#define NSPLIT 2
#define TSPLIT (T_ / NSPLIT)   // 1024 keys per split

// Persistent scratch (no allocations allowed in kernel_launch).
__device__ float g_Q[BT_ * HE_];
__device__ float g_K[BT_ * HE_];
__device__ float g_V[BT_ * HE_];
__device__ float g_Op[NSPLIT * BT_ * HE_];   // unnormalized partial O
__device__ float g_m[NSPLIT * BT_ * H_];     // running max per row
__device__ float g_l[NSPLIT * BT_ * H_];     // running sum per row

// ---------------------------------------------------------------------------
// Packed fp32x2 helpers (Blackwell FFMA2 via PTX f32x2)
// ---------------------------------------------------------------------------
typedef unsigned long long u64;

__device__ __forceinline__ u64 pack2(float lo, float hi) {
    u64 r;
    asm("mov.b64 %0, {%1,%2};" : "=l"(r) : "f"(lo), "f"(hi));
    return r;
}
__device__ __forceinline__ float2 unpack2(u64 v) {
    float2 r;
    asm("mov.b64 {%0,%1}, %2;" : "=f"(r.x), "=f"(r.y) : "l"(v));
    return r;
}
__device__ __forceinline__ void fma2(u64& d, u64 a, u64 b) {
    asm("fma.rn.f32x2 %0, %1, %2, %0;" : "+l"(d) : "l"(a), "l"(b));
}
__device__ __forceinline__ u64 mul2(u64 a, u64 b) {
    u64 r;
    asm("mul.rn.f32x2 %0, %1, %2;" : "=l"(r) : "l"(a), "l"(b));
    return r;
}

// ---------------------------------------------------------------------------
// Projection GEMM (three mats, sel = blockIdx.z): C[8192,1024] = A @ W.
// CTA tile 128x64 (MxN), BK=16, 128 threads, 16x4 micro-tile,
// double-buffered smem, one __syncthreads per k-chunk, prefetch overlapped.
// W span read per kk now amortized over 16 m-rows (2x less LDS per FLOP).
// ---------------------------------------------------------------------------
__global__ __launch_bounds__(128) void proj_gemm(const float* __restrict__ Aq,
                                                 const float* __restrict__ Akv,
                                                 const float* __restrict__ Wq,
                                                 const float* __restrict__ Wk,
                                                 const float* __restrict__ Wv,
                                                 float scale) {
    __shared__ float AsT[2][16][128];   // [buf][k][m-swizzled]  16 KB
    __shared__ float Ws[2][16][68];     // [buf][k][n], padded    8.7 KB

    const int sel = blockIdx.z;
    const float* __restrict__ A = (sel == 0) ? Aq : Akv;
    const float* __restrict__ W = (sel == 0) ? Wq : (sel == 1) ? Wk : Wv;
    float* __restrict__ C = (sel == 0) ? g_Q : (sel == 1) ? g_K : g_V;
    const float cs = (sel == 2) ? 1.0f : scale;

    const int tid = threadIdx.x;
    const int ty = tid >> 4;          // 0..7  (16 rows each)
    const int tx = tid & 15;          // 0..15 (4 cols each)
    const int bm = blockIdx.y << 7;   // 128-row tile
    const int bn = blockIdx.x << 6;   // 64-col tile

    // A loader: thread tid owns row (bm + tid), loads its 16 k per chunk
    const float* Ap = A + (size_t)(bm + tid) * HIN_;
    // W loader: 16 k-rows x 64 cols; thread -> row tid/8, 8 cols at (tid&7)*8
    const int wr = tid >> 3;
    const int wc = (tid & 7) << 3;
    const float* Wp = W + (size_t)wr * HE_ + bn + wc;

    u64 acc[16][2];
#pragma unroll
    for (int i = 0; i < 16; i++) { acc[i][0] = 0ull; acc[i][1] = 0ull; }

    // swizzle: storage col of (k, m) = m ^ (((k>>2)&3)<<2)
    // ---- prologue: chunk 0 ----
    {
        float4 a0 = *(const float4*)(Ap);
        float4 a1 = *(const float4*)(Ap + 4);
        float4 a2 = *(const float4*)(Ap + 8);
        float4 a3 = *(const float4*)(Ap + 12);
        float4 w0 = *(const float4*)(Wp);
        float4 w1 = *(const float4*)(Wp + 4);
        float av[16] = {a0.x, a0.y, a0.z, a0.w, a1.x, a1.y, a1.z, a1.w,
                        a2.x, a2.y, a2.z, a2.w, a3.x, a3.y, a3.z, a3.w};
#pragma unroll
        for (int k = 0; k < 16; k++)
            AsT[0][k][tid ^ (((k >> 2) & 3) << 2)] = av[k];
        *(float4*)&Ws[0][wr][wc] = w0;
        *(float4*)&Ws[0][wr][wc + 4] = w1;
    }
    __syncthreads();

    int buf = 0;
    for (int it = 1; it <= 64; it++) {
        float4 a0, a1, a2, a3, w0, w1;
        if (it < 64) {   // prefetch chunk it
            a0 = *(const float4*)(Ap + it * 16);
            a1 = *(const float4*)(Ap + it * 16 + 4);
            a2 = *(const float4*)(Ap + it * 16 + 8);
            a3 = *(const float4*)(Ap + it * 16 + 12);
            w0 = *(const float4*)(Wp + (size_t)it * 16 * HE_);
            w1 = *(const float4*)(Wp + (size_t)it * 16 * HE_ + 4);
        }

        // compute chunk it-1 from buf
#pragma unroll
        for (int kk = 0; kk < 16; kk++) {
            int cx = ((kk >> 2) & 3) << 2;
            float4 aa0 = *(const float4*)&AsT[buf][kk][((ty << 4) | 0) ^ cx];
            float4 aa1 = *(const float4*)&AsT[buf][kk][((ty << 4) | 4) ^ cx];
            float4 aa2 = *(const float4*)&AsT[buf][kk][((ty << 4) | 8) ^ cx];
            float4 aa3 = *(const float4*)&AsT[buf][kk][((ty << 4) | 12) ^ cx];
            float4 w4 = *(const float4*)&Ws[buf][kk][tx << 2];
            u64 wp0 = pack2(w4.x, w4.y);
            u64 wp1 = pack2(w4.z, w4.w);
            float a[16] = {aa0.x, aa0.y, aa0.z, aa0.w,
                           aa1.x, aa1.y, aa1.z, aa1.w,
                           aa2.x, aa2.y, aa2.z, aa2.w,
                           aa3.x, aa3.y, aa3.z, aa3.w};
#pragma unroll
            for (int i = 0; i < 16; i++) {
                u64 ad = pack2(a[i], a[i]);
                fma2(acc[i][0], ad, wp0);
                fma2(acc[i][1], ad, wp1);
            }
        }

        if (it < 64) {
            int nb = buf ^ 1;
            float av[16] = {a0.x, a0.y, a0.z, a0.w, a1.x, a1.y, a1.z, a1.w,
                            a2.x, a2.y, a2.z, a2.w, a3.x, a3.y, a3.z, a3.w};
#pragma unroll
            for (int k = 0; k < 16; k++)
                AsT[nb][k][tid ^ (((k >> 2) & 3) << 2)] = av[k];
            *(float4*)&Ws[nb][wr][wc] = w0;
            *(float4*)&Ws[nb][wr][wc + 4] = w1;
            __syncthreads();
            buf = nb;
        }
    }

#pragma unroll
    for (int i = 0; i < 16; i++) {
        float2 p0 = unpack2(acc[i][0]);
        float2 p1 = unpack2(acc[i][1]);
        float4 r = make_float4(p0.x * cs, p0.y * cs, p1.x * cs, p1.y * cs);
        *(float4*)&C[(size_t)(bm + (ty << 4) + i) * HE_ + bn + (tx << 2)] = r;
    }
}

// ---------------------------------------------------------------------------
// Flash attention, split-K (unchanged from R11 — known good).
// ---------------------------------------------------------------------------
__global__ __launch_bounds__(128) void flash_attn_split() {
    __shared__ float QsT[64][64];   // swizzled [e][qrow]
    __shared__ float KsT[64][64];   // swizzled [e][krow]; reused plain as P
    __shared__ float Vs[64][64];    // [krow][e]

    const int tid = threadIdx.x;
    const int ty = tid >> 4;
    const int tx = tid & 15;
    const int q0 = blockIdx.x << 6;
    const int h  = blockIdx.y;
    const int b  = blockIdx.z >> 1;
    const int sp = blockIdx.z & 1;

    const size_t baseQ  = ((size_t)(b * T_ + q0) * H_ + h) * E_;
    const size_t baseKV = ((size_t)(b * T_ + sp * TSPLIT) * H_ + h) * E_;

    for (int idx = tid; idx < 1024; idx += 128) {
        int row = idx >> 4;
        int t = idx & 15;
        int c = t << 2;
        float4 v = *(const float4*)(g_Q + baseQ + (size_t)row * HE_ + c);
        int col = (((row >> 2) ^ t) << 2) | (row & 3);
        QsT[c + 0][col] = v.x;
        QsT[c + 1][col] = v.y;
        QsT[c + 2][col] = v.z;
        QsT[c + 3][col] = v.w;
    }

    float m[8], l[8];
    u64 o2[8][2];
#pragma unroll
    for (int i = 0; i < 8; i++) {
        m[i] = -1e30f;
        l[i] = 0.f;
        o2[i][0] = 0ull;
        o2[i][1] = 0ull;
    }

    for (int k0 = 0; k0 < TSPLIT; k0 += 64) {
        __syncthreads();
        for (int idx = tid; idx < 1024; idx += 128) {
            int row = idx >> 4;
            int t = idx & 15;
            int c = t << 2;
            size_t g = baseKV + (size_t)(k0 + row) * HE_ + c;
            float4 kv = *(const float4*)(g_K + g);
            int col = (((row >> 2) ^ t) << 2) | (row & 3);
            KsT[c + 0][col] = kv.x;
            KsT[c + 1][col] = kv.y;
            KsT[c + 2][col] = kv.z;
            KsT[c + 3][col] = kv.w;
            *(float4*)&Vs[row][c] = *(const float4*)(g_V + g);
        }
        __syncthreads();

        u64 s2[8][2];
#pragma unroll
        for (int i = 0; i < 8; i++) { s2[i][0] = 0ull; s2[i][1] = 0ull; }
#pragma unroll 4
        for (int x = 0; x < 16; x++) {
#pragma unroll
            for (int ee = 0; ee < 4; ee++) {
                int e = (x << 2) + ee;
                float4 qa = *(const float4*)&QsT[e][((2 * ty) ^ x) << 2];
                float4 qb = *(const float4*)&QsT[e][((2 * ty + 1) ^ x) << 2];
                float4 k4 = *(const float4*)&KsT[e][(tx ^ x) << 2];
                u64 kp0 = pack2(k4.x, k4.y);
                u64 kp1 = pack2(k4.z, k4.w);
                float q[8] = {qa.x, qa.y, qa.z, qa.w, qb.x, qb.y, qb.z, qb.w};
#pragma unroll
                for (int i = 0; i < 8; i++) {
                    u64 qd = pack2(q[i], q[i]);
                    fma2(s2[i][0], qd, kp0);
                    fma2(s2[i][1], qd, kp1);
                }
            }
        }

        float s[8][4];
#pragma unroll
        for (int i = 0; i < 8; i++) {
            float2 p0 = unpack2(s2[i][0]);
            float2 p1 = unpack2(s2[i][1]);
            s[i][0] = p0.x; s[i][1] = p0.y; s[i][2] = p1.x; s[i][3] = p1.y;
        }
#pragma unroll
        for (int i = 0; i < 8; i++) {
            float mx = fmaxf(fmaxf(s[i][0], s[i][1]), fmaxf(s[i][2], s[i][3]));
#pragma unroll
            for (int off = 8; off >= 1; off >>= 1)
                mx = fmaxf(mx, __shfl_xor_sync(0xffffffffu, mx, off));
            float mnew = fmaxf(m[i], mx);
            float corr = __expf(m[i] - mnew);
            float rs = 0.f;
#pragma unroll
            for (int j = 0; j < 4; j++) {
                s[i][j] = __expf(s[i][j] - mnew);
                rs += s[i][j];
            }
#pragma unroll
            for (int off = 8; off >= 1; off >>= 1)
                rs += __shfl_xor_sync(0xffffffffu, rs, off);
            l[i] = l[i] * corr + rs;
            m[i] = mnew;
            u64 cd = pack2(corr, corr);
            o2[i][0] = mul2(o2[i][0], cd);
            o2[i][1] = mul2(o2[i][1], cd);
        }

        __syncthreads();
#pragma unroll
        for (int i = 0; i < 8; i++)
            *(float4*)&KsT[(ty << 3) + i][tx << 2] =
                make_float4(s[i][0], s[i][1], s[i][2], s[i][3]);
        __syncthreads();

#pragma unroll 4
        for (int k = 0; k < 64; k += 4) {
            u64 vp[4][2];
#pragma unroll
            for (int kk = 0; kk < 4; kk++) {
                float4 v4 = *(const float4*)&Vs[k + kk][tx << 2];
                vp[kk][0] = pack2(v4.x, v4.y);
                vp[kk][1] = pack2(v4.z, v4.w);
            }
#pragma unroll
            for (int i = 0; i < 8; i++) {
                float4 p4 = *(const float4*)&KsT[(ty << 3) + i][k];
                float p[4] = {p4.x, p4.y, p4.z, p4.w};
#pragma unroll
                for (int kk = 0; kk < 4; kk++) {
                    u64 pd = pack2(p[kk], p[kk]);
                    fma2(o2[i][0], pd, vp[kk][0]);
                    fma2(o2[i][1], pd, vp[kk][1]);
                }
            }
        }
    }

    const size_t opBase = (size_t)sp * BT_ * HE_;
    const size_t mlBase = (size_t)sp * BT_ * H_;
#pragma unroll
    for (int i = 0; i < 8; i++) {
        int row = q0 + (ty << 3) + i;
        float2 p0 = unpack2(o2[i][0]);
        float2 p1 = unpack2(o2[i][1]);
        *(float4*)&g_Op[opBase + ((size_t)(b * T_ + row) * H_ + h) * E_ +
                        (tx << 2)] = make_float4(p0.x, p0.y, p1.x, p1.y);
        if (tx == 0) {
            size_t mi = mlBase + (size_t)(b * T_ + row) * H_ + h;
            g_m[mi] = m[i];
            g_l[mi] = l[i];
        }
    }
}

// ---------------------------------------------------------------------------
// Combine (unchanged from R11).
// ---------------------------------------------------------------------------
__global__ __launch_bounds__(256) void flash_combine(float* __restrict__ Out) {
    int idx = blockIdx.x * 256 + threadIdx.x;   // float4 index
    int rowh = idx >> 4;                         // (b*T+t)*H + h
    float m0 = g_m[rowh];
    float m1 = g_m[BT_ * H_ + rowh];
    float l0 = g_l[rowh];
    float l1 = g_l[BT_ * H_ + rowh];
    float M = fmaxf(m0, m1);
    float w0 = __expf(m0 - M);
    float w1 = __expf(m1 - M);
    float inv = 1.0f / (l0 * w0 + l1 * w1);

    const float4* Op4 = (const float4*)g_Op;
    float4 o0 = Op4[idx];
    float4 o1 = Op4[(BT_ * HE_ / 4) + idx];
    float4 r;
    r.x = (o0.x * w0 + o1.x * w1) * inv;
    r.y = (o0.y * w0 + o1.y * w1) * inv;
    r.z = (o0.z * w0 + o1.z * w1) * inv;
    r.w = (o0.w * w0 + o1.w * w1) * inv;
    ((float4*)Out)[idx] = r;
}

// ---------------------------------------------------------------------------
extern "C" void kernel_launch(void* const* d_in, const int* in_sizes, int n_in,
                              void* d_out, int out_size) {
    const float* query     = (const float*)d_in[0];
    const float* key_value = (const float*)d_in[1];
    const float* Wq        = (const float*)d_in[2];
    const float* Wk        = (const float*)d_in[3];
    const float* Wv        = (const float*)d_in[4];
    float* out = (float*)d_out;

    const float scale = 0.35355339059327379f;  // 64^(-1/4)

    dim3 gproj(HE_ / 64, BT_ / 128, 3);        // (16, 64, 3)
    proj_gemm<<<gproj, 128>>>(query, key_value, Wq, Wk, Wv, scale);

    dim3 gattn(T_ / 64, H_, B_ * NSPLIT);      // (32, 16, 8)
    flash_attn_split<<<gattn, 128>>>();

    flash_combine<<<BT_ * HE_ / 4 / 256, 256>>>(out);
}

// round 13
// speedup vs baseline: 1.6459x; 1.0054x over previous
#include <cuda_runtime.h>
#include <cstdint>

#define B_   4
#define T_   2048
#define HIN_ 1024
#define H_   16
#define E_   64
#define HE_  (H_ * E_)   // 1024
#define BT_  (B_ * T_)   // 8192
#define NSPLIT 2
#define TSPLIT (T_ / NSPLIT)   // 1024 keys per split

// Persistent scratch (no allocations allowed in kernel_launch).
__device__ float g_Q[BT_ * HE_];
__device__ float g_K[BT_ * HE_];
__device__ float g_V[BT_ * HE_];
__device__ float g_Op[NSPLIT * BT_ * HE_];   // unnormalized partial O
__device__ float g_m[NSPLIT * BT_ * H_];     // running max per row
__device__ float g_l[NSPLIT * BT_ * H_];     // running sum per row

// ---------------------------------------------------------------------------
// Packed fp32x2 helpers (Blackwell FFMA2 via PTX f32x2)
// ---------------------------------------------------------------------------
typedef unsigned long long u64;

__device__ __forceinline__ u64 pack2(float lo, float hi) {
    u64 r;
    asm("mov.b64 %0, {%1,%2};" : "=l"(r) : "f"(lo), "f"(hi));
    return r;
}
__device__ __forceinline__ float2 unpack2(u64 v) {
    float2 r;
    asm("mov.b64 {%0,%1}, %2;" : "=f"(r.x), "=f"(r.y) : "l"(v));
    return r;
}
__device__ __forceinline__ void fma2(u64& d, u64 a, u64 b) {
    asm("fma.rn.f32x2 %0, %1, %2, %0;" : "+l"(d) : "l"(a), "l"(b));
}
__device__ __forceinline__ u64 mul2(u64 a, u64 b) {
    u64 r;
    asm("mul.rn.f32x2 %0, %1, %2;" : "=l"(r) : "l"(a), "l"(b));
    return r;
}

// ---------------------------------------------------------------------------
// Projection GEMM, KV-fused:
//   z = 0: C=Q from (query, Wq), one output.
//   z = 1: C={K,V} from (key_value, {Wk,Wv}) — A tile loaded ONCE, two W
//          tiles, two accumulator sets. LDS per unit work drops 1.5x.
// CTA tile 64x64, BK=16, 128 threads, 8x4 micro-tile (per output),
// double-buffered smem, one __syncthreads per k-chunk.
// ---------------------------------------------------------------------------
__global__ __launch_bounds__(128) void proj_gemm(const float* __restrict__ Aq,
                                                 const float* __restrict__ Akv,
                                                 const float* __restrict__ Wq,
                                                 const float* __restrict__ Wk,
                                                 const float* __restrict__ Wv,
                                                 float scale) {
    __shared__ float AsT[2][16][64];      // [buf][k][m-swizzled]
    __shared__ float Ws[2][2][16][68];    // [buf][mat][k][n], padded rows

    const int fused = blockIdx.z;         // 0: Q, 1: K+V
    const float* __restrict__ A  = fused ? Akv : Aq;
    const float* __restrict__ W0 = fused ? Wk : Wq;
    const float* __restrict__ W1 = Wv;    // used only when fused
    float* __restrict__ C0 = fused ? g_K : g_Q;
    float* __restrict__ C1 = g_V;

    const int tid = threadIdx.x;
    const int ty = tid >> 4;          // 0..7  (8 rows each)
    const int tx = tid & 15;          // 0..15 (4 cols each)
    const int bm = blockIdx.y << 6;
    const int bn = blockIdx.x << 6;

    // A loader: 64 rows x 16 k; thread -> row tid/2, 8 k at (tid&1)*8
    const int ar = tid >> 1;
    const int ac = (tid & 1) << 3;
    // W loader: 16 k-rows x 64 cols; thread -> row tid/8, 8 cols at (tid&7)*8
    const int wr = tid >> 3;
    const int wc = (tid & 7) << 3;

    const float* Ap  = A + (size_t)(bm + ar) * HIN_ + ac;
    const float* W0p = W0 + (size_t)wr * HE_ + bn + wc;
    const float* W1p = W1 + (size_t)wr * HE_ + bn + wc;

    u64 acc0[8][2], acc1[8][2];
#pragma unroll
    for (int i = 0; i < 8; i++) {
        acc0[i][0] = 0ull; acc0[i][1] = 0ull;
        acc1[i][0] = 0ull; acc1[i][1] = 0ull;
    }

    // swizzle: storage col of (k, m) = m ^ (((k>>2)&3)<<2)
    {   // prologue: chunk 0
        float4 a0 = *(const float4*)(Ap);
        float4 a1 = *(const float4*)(Ap + 4);
        float av[8] = {a0.x, a0.y, a0.z, a0.w, a1.x, a1.y, a1.z, a1.w};
#pragma unroll
        for (int j = 0; j < 8; j++) {
            int k = ac + j;
            AsT[0][k][ar ^ (((k >> 2) & 3) << 2)] = av[j];
        }
        *(float4*)&Ws[0][0][wr][wc]     = *(const float4*)(W0p);
        *(float4*)&Ws[0][0][wr][wc + 4] = *(const float4*)(W0p + 4);
        if (fused) {
            *(float4*)&Ws[0][1][wr][wc]     = *(const float4*)(W1p);
            *(float4*)&Ws[0][1][wr][wc + 4] = *(const float4*)(W1p + 4);
        }
    }
    __syncthreads();

    int buf = 0;
    for (int it = 1; it <= 64; it++) {
        float4 a0, a1, wa0, wa1, wb0, wb1;
        if (it < 64) {   // prefetch chunk it
            a0 = *(const float4*)(Ap + it * 16);
            a1 = *(const float4*)(Ap + it * 16 + 4);
            wa0 = *(const float4*)(W0p + (size_t)it * 16 * HE_);
            wa1 = *(const float4*)(W0p + (size_t)it * 16 * HE_ + 4);
            if (fused) {
                wb0 = *(const float4*)(W1p + (size_t)it * 16 * HE_);
                wb1 = *(const float4*)(W1p + (size_t)it * 16 * HE_ + 4);
            }
        }

        // compute chunk it-1 from buf
#pragma unroll
        for (int kk = 0; kk < 16; kk++) {
            int cx = ((kk >> 2) & 3) << 2;
            float4 aa0 = *(const float4*)&AsT[buf][kk][(ty << 3) ^ cx];
            float4 aa1 = *(const float4*)&AsT[buf][kk][((ty << 3) + 4) ^ cx];
            float4 w4 = *(const float4*)&Ws[buf][0][kk][tx << 2];
            u64 wp0 = pack2(w4.x, w4.y);
            u64 wp1 = pack2(w4.z, w4.w);
            float a[8] = {aa0.x, aa0.y, aa0.z, aa0.w,
                          aa1.x, aa1.y, aa1.z, aa1.w};
#pragma unroll
            for (int i = 0; i < 8; i++) {
                u64 ad = pack2(a[i], a[i]);
                fma2(acc0[i][0], ad, wp0);
                fma2(acc0[i][1], ad, wp1);
            }
            if (fused) {
                float4 v4 = *(const float4*)&Ws[buf][1][kk][tx << 2];
                u64 vp0 = pack2(v4.x, v4.y);
                u64 vp1 = pack2(v4.z, v4.w);
#pragma unroll
                for (int i = 0; i < 8; i++) {
                    u64 ad = pack2(a[i], a[i]);
                    fma2(acc1[i][0], ad, vp0);
                    fma2(acc1[i][1], ad, vp1);
                }
            }
        }

        if (it < 64) {
            int nb = buf ^ 1;
            float av[8] = {a0.x, a0.y, a0.z, a0.w, a1.x, a1.y, a1.z, a1.w};
#pragma unroll
            for (int j = 0; j < 8; j++) {
                int k = ac + j;
                AsT[nb][k][ar ^ (((k >> 2) & 3) << 2)] = av[j];
            }
            *(float4*)&Ws[nb][0][wr][wc]     = wa0;
            *(float4*)&Ws[nb][0][wr][wc + 4] = wa1;
            if (fused) {
                *(float4*)&Ws[nb][1][wr][wc]     = wb0;
                *(float4*)&Ws[nb][1][wr][wc + 4] = wb1;
            }
            __syncthreads();
            buf = nb;
        }
    }

    // Epilogue: Q and K carry the softmax scale; V is unscaled.
#pragma unroll
    for (int i = 0; i < 8; i++) {
        float2 p0 = unpack2(acc0[i][0]);
        float2 p1 = unpack2(acc0[i][1]);
        float4 r = make_float4(p0.x * scale, p0.y * scale,
                               p1.x * scale, p1.y * scale);
        *(float4*)&C0[(size_t)(bm + (ty << 3) + i) * HE_ + bn + (tx << 2)] = r;
    }
    if (fused) {
#pragma unroll
        for (int i = 0; i < 8; i++) {
            float2 p0 = unpack2(acc1[i][0]);
            float2 p1 = unpack2(acc1[i][1]);
            float4 r = make_float4(p0.x, p0.y, p1.x, p1.y);
            *(float4*)&C1[(size_t)(bm + (ty << 3) + i) * HE_ + bn + (tx << 2)] = r;
        }
    }
}

// ---------------------------------------------------------------------------
// Flash attention, split-K (unchanged from R11/R12 — known good).
// ---------------------------------------------------------------------------
__global__ __launch_bounds__(128) void flash_attn_split() {
    __shared__ float QsT[64][64];   // swizzled [e][qrow]
    __shared__ float KsT[64][64];   // swizzled [e][krow]; reused plain as P
    __shared__ float Vs[64][64];    // [krow][e]

    const int tid = threadIdx.x;
    const int ty = tid >> 4;
    const int tx = tid & 15;
    const int q0 = blockIdx.x << 6;
    const int h  = blockIdx.y;
    const int b  = blockIdx.z >> 1;
    const int sp = blockIdx.z & 1;

    const size_t baseQ  = ((size_t)(b * T_ + q0) * H_ + h) * E_;
    const size_t baseKV = ((size_t)(b * T_ + sp * TSPLIT) * H_ + h) * E_;

    for (int idx = tid; idx < 1024; idx += 128) {
        int row = idx >> 4;
        int t = idx & 15;
        int c = t << 2;
        float4 v = *(const float4*)(g_Q + baseQ + (size_t)row * HE_ + c);
        int col = (((row >> 2) ^ t) << 2) | (row & 3);
        QsT[c + 0][col] = v.x;
        QsT[c + 1][col] = v.y;
        QsT[c + 2][col] = v.z;
        QsT[c + 3][col] = v.w;
    }

    float m[8], l[8];
    u64 o2[8][2];
#pragma unroll
    for (int i = 0; i < 8; i++) {
        m[i] = -1e30f;
        l[i] = 0.f;
        o2[i][0] = 0ull;
        o2[i][1] = 0ull;
    }

    for (int k0 = 0; k0 < TSPLIT; k0 += 64) {
        __syncthreads();
        for (int idx = tid; idx < 1024; idx += 128) {
            int row = idx >> 4;
            int t = idx & 15;
            int c = t << 2;
            size_t g = baseKV + (size_t)(k0 + row) * HE_ + c;
            float4 kv = *(const float4*)(g_K + g);
            int col = (((row >> 2) ^ t) << 2) | (row & 3);
            KsT[c + 0][col] = kv.x;
            KsT[c + 1][col] = kv.y;
            KsT[c + 2][col] = kv.z;
            KsT[c + 3][col] = kv.w;
            *(float4*)&Vs[row][c] = *(const float4*)(g_V + g);
        }
        __syncthreads();

        u64 s2[8][2];
#pragma unroll
        for (int i = 0; i < 8; i++) { s2[i][0] = 0ull; s2[i][1] = 0ull; }
#pragma unroll 4
        for (int x = 0; x < 16; x++) {
#pragma unroll
            for (int ee = 0; ee < 4; ee++) {
                int e = (x << 2) + ee;
                float4 qa = *(const float4*)&QsT[e][((2 * ty) ^ x) << 2];
                float4 qb = *(const float4*)&QsT[e][((2 * ty + 1) ^ x) << 2];
                float4 k4 = *(const float4*)&KsT[e][(tx ^ x) << 2];
                u64 kp0 = pack2(k4.x, k4.y);
                u64 kp1 = pack2(k4.z, k4.w);
                float q[8] = {qa.x, qa.y, qa.z, qa.w, qb.x, qb.y, qb.z, qb.w};
#pragma unroll
                for (int i = 0; i < 8; i++) {
                    u64 qd = pack2(q[i], q[i]);
                    fma2(s2[i][0], qd, kp0);
                    fma2(s2[i][1], qd, kp1);
                }
            }
        }

        float s[8][4];
#pragma unroll
        for (int i = 0; i < 8; i++) {
            float2 p0 = unpack2(s2[i][0]);
            float2 p1 = unpack2(s2[i][1]);
            s[i][0] = p0.x; s[i][1] = p0.y; s[i][2] = p1.x; s[i][3] = p1.y;
        }
#pragma unroll
        for (int i = 0; i < 8; i++) {
            float mx = fmaxf(fmaxf(s[i][0], s[i][1]), fmaxf(s[i][2], s[i][3]));
#pragma unroll
            for (int off = 8; off >= 1; off >>= 1)
                mx = fmaxf(mx, __shfl_xor_sync(0xffffffffu, mx, off));
            float mnew = fmaxf(m[i], mx);
            float corr = __expf(m[i] - mnew);
            float rs = 0.f;
#pragma unroll
            for (int j = 0; j < 4; j++) {
                s[i][j] = __expf(s[i][j] - mnew);
                rs += s[i][j];
            }
#pragma unroll
            for (int off = 8; off >= 1; off >>= 1)
                rs += __shfl_xor_sync(0xffffffffu, rs, off);
            l[i] = l[i] * corr + rs;
            m[i] = mnew;
            u64 cd = pack2(corr, corr);
            o2[i][0] = mul2(o2[i][0], cd);
            o2[i][1] = mul2(o2[i][1], cd);
        }

        __syncthreads();
#pragma unroll
        for (int i = 0; i < 8; i++)
            *(float4*)&KsT[(ty << 3) + i][tx << 2] =
                make_float4(s[i][0], s[i][1], s[i][2], s[i][3]);
        __syncthreads();

#pragma unroll 4
        for (int k = 0; k < 64; k += 4) {
            u64 vp[4][2];
#pragma unroll
            for (int kk = 0; kk < 4; kk++) {
                float4 v4 = *(const float4*)&Vs[k + kk][tx << 2];
                vp[kk][0] = pack2(v4.x, v4.y);
                vp[kk][1] = pack2(v4.z, v4.w);
            }
#pragma unroll
            for (int i = 0; i < 8; i++) {
                float4 p4 = *(const float4*)&KsT[(ty << 3) + i][k];
                float p[4] = {p4.x, p4.y, p4.z, p4.w};
#pragma unroll
                for (int kk = 0; kk < 4; kk++) {
                    u64 pd = pack2(p[kk], p[kk]);
                    fma2(o2[i][0], pd, vp[kk][0]);
                    fma2(o2[i][1], pd, vp[kk][1]);
                }
            }
        }
    }

    const size_t opBase = (size_t)sp * BT_ * HE_;
    const size_t mlBase = (size_t)sp * BT_ * H_;
#pragma unroll
    for (int i = 0; i < 8; i++) {
        int row = q0 + (ty << 3) + i;
        float2 p0 = unpack2(o2[i][0]);
        float2 p1 = unpack2(o2[i][1]);
        *(float4*)&g_Op[opBase + ((size_t)(b * T_ + row) * H_ + h) * E_ +
                        (tx << 2)] = make_float4(p0.x, p0.y, p1.x, p1.y);
        if (tx == 0) {
            size_t mi = mlBase + (size_t)(b * T_ + row) * H_ + h;
            g_m[mi] = m[i];
            g_l[mi] = l[i];
        }
    }
}

// ---------------------------------------------------------------------------
// Combine (unchanged).
// ---------------------------------------------------------------------------
__global__ __launch_bounds__(256) void flash_combine(float* __restrict__ Out) {
    int idx = blockIdx.x * 256 + threadIdx.x;   // float4 index
    int rowh = idx >> 4;                         // (b*T+t)*H + h
    float m0 = g_m[rowh];
    float m1 = g_m[BT_ * H_ + rowh];
    float l0 = g_l[rowh];
    float l1 = g_l[BT_ * H_ + rowh];
    float M = fmaxf(m0, m1);
    float w0 = __expf(m0 - M);
    float w1 = __expf(m1 - M);
    float inv = 1.0f / (l0 * w0 + l1 * w1);

    const float4* Op4 = (const float4*)g_Op;
    float4 o0 = Op4[idx];
    float4 o1 = Op4[(BT_ * HE_ / 4) + idx];
    float4 r;
    r.x = (o0.x * w0 + o1.x * w1) * inv;
    r.y = (o0.y * w0 + o1.y * w1) * inv;
    r.z = (o0.z * w0 + o1.z * w1) * inv;
    r.w = (o0.w * w0 + o1.w * w1) * inv;
    ((float4*)Out)[idx] = r;
}

// ---------------------------------------------------------------------------
extern "C" void kernel_launch(void* const* d_in, const int* in_sizes, int n_in,
                              void* d_out, int out_size) {
    const float* query     = (const float*)d_in[0];
    const float* key_value = (const float*)d_in[1];
    const float* Wq        = (const float*)d_in[2];
    const float* Wk        = (const float*)d_in[3];
    const float* Wv        = (const float*)d_in[4];
    float* out = (float*)d_out;

    const float scale = 0.35355339059327379f;  // 64^(-1/4)

    dim3 gproj(HE_ / 64, BT_ / 64, 2);         // (16, 128, 2): z0=Q, z1=K+V
    proj_gemm<<<gproj, 128>>>(query, key_value, Wq, Wk, Wv, scale);

    dim3 gattn(T_ / 64, H_, B_ * NSPLIT);      // (32, 16, 8)
    flash_attn_split<<<gattn, 128>>>();

    flash_combine<<<BT_ * HE_ / 4 / 256, 256>>>(out);
}